// round 6
// baseline (speedup 1.0000x reference)
#include <cuda_runtime.h>
#include <math.h>

// Problem constants (fixed by setup_inputs)
#define BB   256          // batch
#define TT   512          // observed sequence length
#define FUT  64           // future steps
#define KT   64           // K-chunk for GEMM staging
#define NBLK 128          // persistent grid size (<=148 SMs -> all co-resident)

// ---------------------------------------------------------------------------
// Persistent device scratch (module-load allocated; no runtime allocations)
// ---------------------------------------------------------------------------
__device__ float g_SA[BB * 1024];        // ping state  [h0 (512) | h1 (512)]
__device__ float g_SB[BB * 1024];        // pong state
__device__ float g_C [BB * 1024];        // cell states [c0 | c1]
__device__ float g_W1[2048 * 1024];      // [w_ih1 | w_hh1] concat, row-major
__device__ float g_WP[2048 * 1024];      // [pw_ih1 | pw_hh1] concat
__device__ float g_HP[2][16][BB];        // head partial sums (per u-tile), ping-pong
__device__ unsigned g_cnt = 0;           // grid barrier arrival counter
__device__ unsigned g_gen = 0;           // grid barrier generation

// ---------------------------------------------------------------------------
// Software grid barrier (sense-reversing; all CTAs co-resident by construction)
// ---------------------------------------------------------------------------
__device__ __forceinline__ void grid_sync() {
    __syncthreads();
    if (threadIdx.x == 0) {
        __threadfence();
        const unsigned gen = atomicAdd(&g_gen, 0u);
        if (atomicAdd(&g_cnt, 1u) == gridDim.x - 1u) {
            atomicExch(&g_cnt, 0u);
            __threadfence();
            atomicAdd(&g_gen, 1u);
        } else {
            while (atomicAdd(&g_gen, 0u) == gen) { }
        }
        __threadfence();
    }
    __syncthreads();
}

// ---------------------------------------------------------------------------
// Fused LSTM step (device function, single SASS copy via noinline):
//   gates = bias + [x-term] + hin @ W^T ; pointwise c/h update; optional head.
//   W      : [2048][K] row-major (torch gate order i,f,g,o; 512 rows per gate)
//   hin    : state rows of width 1024; uses hin[b*1024 + k], k in [0,K)
//   x modes: xw==null -> none; xpart!=null -> xv = sum16 partials + bias
//            (also writes out column); else xv = xs[b*xstride]
//   headw  : if non-null, write per-u-tile partial dots h.headw into hpOut
// CTA (ublk=blockIdx&15, bblk=blockIdx>>4): 32 batch x 128 gate-rows tile.
// ---------------------------------------------------------------------------
#define MMA4(hv, comp)                                                                   \
    a00 += hv.x * w0.comp; a01 += hv.x * w1.comp; a02 += hv.x * w2.comp; a03 += hv.x * w3.comp; \
    a10 += hv.y * w0.comp; a11 += hv.y * w1.comp; a12 += hv.y * w2.comp; a13 += hv.y * w3.comp; \
    a20 += hv.z * w0.comp; a21 += hv.z * w1.comp; a22 += hv.z * w2.comp; a23 += hv.z * w3.comp; \
    a30 += hv.w * w0.comp; a31 += hv.w * w1.comp; a32 += hv.w * w2.comp; a33 += hv.w * w3.comp;

__device__ __noinline__ void lstm_step(
    const float* __restrict__ W, int K,
    const float* __restrict__ hin,
    const float* __restrict__ bih, const float* __restrict__ bhh,
    const float* __restrict__ xs, int xstride,
    const float* __restrict__ xw,
    const float (* __restrict__ xpart)[BB], const float* __restrict__ xbias_p,
    float* __restrict__ outp,
    float* __restrict__ cbuf, float* __restrict__ hout,
    const float* __restrict__ headw, float (* __restrict__ hpOut)[BB],
    char* raw, float* xsm)
{
    float (*ws)[KT + 4] = reinterpret_cast<float (*)[KT + 4]>(raw);
    float (*hs)[36]     = reinterpret_cast<float (*)[36]>(raw + 128 * (KT + 4) * 4);
    float (*gsm)[33]    = reinterpret_cast<float (*)[33]>(raw);

    const int tid  = threadIdx.x;
    const int ublk = blockIdx.x & 15;
    const int bblk = blockIdx.x >> 4;
    const int u0   = ublk * 32;
    const int b0   = bblk * 32;
    const int tx4  = (tid & 7) * 4;
    const int ty4  = (tid >> 3) * 4;

    __syncthreads();   // protect smem reuse against previous call's tail reads

    // decode-mode scalar input: xv[b] = sum of 16 u-tile partials + head bias
    if (xpart != nullptr && tid < 32) {
        float s = xbias_p[0];
        #pragma unroll
        for (int ut = 0; ut < 16; ut++) s += xpart[ut][b0 + tid];
        xsm[tid] = s;
        if (ublk == 0) outp[(size_t)(b0 + tid) * FUT] = s;   // publish out column
    }

    float a00 = 0.f, a01 = 0.f, a02 = 0.f, a03 = 0.f;
    float a10 = 0.f, a11 = 0.f, a12 = 0.f, a13 = 0.f;
    float a20 = 0.f, a21 = 0.f, a22 = 0.f, a23 = 0.f;
    float a30 = 0.f, a31 = 0.f, a32 = 0.f, a33 = 0.f;

    // W staging assignment: thread -> (local row sr, 32-col half of the K chunk)
    const int sr    = tid >> 1;
    const int shalf = tid & 1;
    const int sg    = sr >> 5;
    const int suu   = sr & 31;
    const float* wrow = W + (size_t)(sg * 512 + u0 + suu) * K + shalf * 32;

    for (int k0 = 0; k0 < K; k0 += KT) {
        #pragma unroll
        for (int i = 0; i < 8; i++) {
            float4 v = *(const float4*)(wrow + k0 + i * 4);
            *(float4*)&ws[sr][shalf * 32 + i * 4] = v;
        }
        #pragma unroll
        for (int rep = 0; rep < 2; rep++) {
            int f  = tid + rep * 256;
            int r  = f & 31;
            int kq = f >> 5;
            float4 v = *(const float4*)(hin + (size_t)(b0 + r) * 1024 + k0 + kq * 4);
            hs[kq * 4 + 0][r] = v.x;
            hs[kq * 4 + 1][r] = v.y;
            hs[kq * 4 + 2][r] = v.z;
            hs[kq * 4 + 3][r] = v.w;
        }
        __syncthreads();

        #pragma unroll 8
        for (int kk = 0; kk < KT; kk += 4) {
            const float4 ha = *(const float4*)&hs[kk + 0][tx4];
            const float4 hb = *(const float4*)&hs[kk + 1][tx4];
            const float4 hc = *(const float4*)&hs[kk + 2][tx4];
            const float4 hd = *(const float4*)&hs[kk + 3][tx4];
            const float4 w0 = *(const float4*)&ws[ty4 + 0][kk];
            const float4 w1 = *(const float4*)&ws[ty4 + 1][kk];
            const float4 w2 = *(const float4*)&ws[ty4 + 2][kk];
            const float4 w3 = *(const float4*)&ws[ty4 + 3][kk];
            MMA4(ha, x); MMA4(hb, y); MMA4(hc, z); MMA4(hd, w);
        }
        __syncthreads();
    }

    // gate exchange through SMEM: gsm[local gate row][local batch]
    gsm[ty4 + 0][tx4 + 0] = a00; gsm[ty4 + 1][tx4 + 0] = a01; gsm[ty4 + 2][tx4 + 0] = a02; gsm[ty4 + 3][tx4 + 0] = a03;
    gsm[ty4 + 0][tx4 + 1] = a10; gsm[ty4 + 1][tx4 + 1] = a11; gsm[ty4 + 2][tx4 + 1] = a12; gsm[ty4 + 3][tx4 + 1] = a13;
    gsm[ty4 + 0][tx4 + 2] = a20; gsm[ty4 + 1][tx4 + 2] = a21; gsm[ty4 + 2][tx4 + 2] = a22; gsm[ty4 + 3][tx4 + 2] = a23;
    gsm[ty4 + 0][tx4 + 3] = a30; gsm[ty4 + 1][tx4 + 3] = a31; gsm[ty4 + 2][tx4 + 3] = a32; gsm[ty4 + 3][tx4 + 3] = a33;
    __syncthreads();

    // pointwise LSTM update: thread (uu, bq) handles unit jb for 4 batches
    const int uu = tid & 31;
    const int bq = tid >> 5;
    const int jb = u0 + uu;

    const bool hasx = (xw != nullptr);
    float wxi = 0.f, wxf = 0.f, wxg = 0.f, wxo = 0.f;
    if (hasx) {
        wxi = xw[jb]; wxf = xw[512 + jb]; wxg = xw[1024 + jb]; wxo = xw[1536 + jb];
    }
    const float bi_ = bih[jb]        + bhh[jb];
    const float bf_ = bih[512 + jb]  + bhh[512 + jb];
    const float bg_ = bih[1024 + jb] + bhh[1024 + jb];
    const float bo_ = bih[1536 + jb] + bhh[1536 + jb];

    float hvals[4];
    #pragma unroll
    for (int p = 0; p < 4; p++) {
        const int bb = bq * 4 + p;
        const int b  = b0 + bb;
        float xv = 0.f;
        if (hasx) xv = (xpart != nullptr) ? xsm[bb] : xs[(size_t)b * xstride];

        float vi = gsm[uu][bb]      + bi_ + xv * wxi;
        float vf = gsm[32 + uu][bb] + bf_ + xv * wxf;
        float vg = gsm[64 + uu][bb] + bg_ + xv * wxg;
        float vo = gsm[96 + uu][bb] + bo_ + xv * wxo;

        const float ig = 1.f / (1.f + expf(-vi));
        const float fg = 1.f / (1.f + expf(-vf));
        const float gg = tanhf(vg);
        const float og = 1.f / (1.f + expf(-vo));

        const size_t idx = (size_t)b * 1024 + jb;
        const float cn = fg * cbuf[idx] + ig * gg;
        cbuf[idx] = cn;
        const float hn = og * tanhf(cn);
        hout[idx] = hn;
        hvals[p] = hn;
    }

    // optional head: deterministic per-u-tile partial dot products
    if (headw != nullptr) {
        const float fwv = headw[jb];
        #pragma unroll
        for (int p = 0; p < 4; p++) {
            float v = hvals[p] * fwv;
            #pragma unroll
            for (int off = 16; off > 0; off >>= 1)
                v += __shfl_xor_sync(0xffffffffu, v, off);
            if (uu == 0) hpOut[ublk][b0 + bq * 4 + p] = v;
        }
    }
}

// ---------------------------------------------------------------------------
// One persistent kernel = one graph node. Internal grid barriers sequence the
// recurrence. Warmup is software-pipelined: phase t = { L1(t-1), L0(t) } with
// a single barrier per phase.
// ---------------------------------------------------------------------------
__global__ __launch_bounds__(256, 1) void lstm_persist(
    const float* __restrict__ x,
    const float* __restrict__ w_ih0, const float* __restrict__ w_hh0,
    const float* __restrict__ b_ih0, const float* __restrict__ b_hh0,
    const float* __restrict__ w_ih1, const float* __restrict__ w_hh1,
    const float* __restrict__ b_ih1, const float* __restrict__ b_hh1,
    const float* __restrict__ fc_w,  const float* __restrict__ fc_b,
    const float* __restrict__ pw_ih0, const float* __restrict__ pw_hh0,
    const float* __restrict__ pb_ih0, const float* __restrict__ pb_hh0,
    const float* __restrict__ pw_ih1, const float* __restrict__ pw_hh1,
    const float* __restrict__ pb_ih1, const float* __restrict__ pb_hh1,
    const float* __restrict__ pfc_w,  const float* __restrict__ pfc_b,
    float* __restrict__ out)
{
    __shared__ __align__(16) char raw[44032];
    __shared__ float xsm[32];

    const int tid  = threadIdx.x;
    const int gtid = blockIdx.x * 256 + tid;
    const int nthr = NBLK * 256;

    // ---- init: zero states, build concat weights ----
    for (int i = gtid; i < BB * 1024; i += nthr) {
        g_SA[i] = 0.f; g_SB[i] = 0.f; g_C[i] = 0.f;
    }
    for (int i = gtid; i < 2048 * 1024; i += nthr) {
        const int j = i >> 10, k = i & 1023;
        g_W1[i] = (k < 512) ? w_ih1[j * 512 + k] : w_hh1[j * 512 + (k - 512)];
        g_WP[i] = (k < 512) ? pw_ih1[j * 512 + k] : pw_hh1[j * 512 + (k - 512)];
    }
    grid_sync();

    // ---- phase 0: L0(0) reads zeros in SA, writes h0(0) into SB[0:512] ----
    lstm_step(w_hh0, 512, g_SA, b_ih0, b_hh0, x, TT, w_ih0,
              nullptr, nullptr, nullptr, g_C, g_SB, nullptr, nullptr, raw, xsm);
    grid_sync();

    // ---- warmup phases t = 1..512: { L1(t-1), L0(t) }, one barrier each ----
    for (int t = 1; t <= TT; t++) {
        float* P = (t & 1) ? g_SB : g_SA;   // read buffer:  [h0(t-1) | h1(t-2)]
        float* Q = (t & 1) ? g_SA : g_SB;   // write buffer
        const bool last = (t == TT);
        // L1(t-1): reads P full, writes h1(t-1) -> Q+512 (head partials on last)
        lstm_step(g_W1, 1024, P, b_ih1, b_hh1, nullptr, 0, nullptr,
                  nullptr, nullptr, nullptr, g_C + 512, Q + 512,
                  last ? fc_w : nullptr, g_HP[0], raw, xsm);
        if (!last) {
            // L0(t): reads P[0:512], writes h0(t) -> Q[0:512]
            lstm_step(w_hh0, 512, P, b_ih0, b_hh0, x + t, TT, w_ih0,
                      nullptr, nullptr, nullptr, g_C, Q, nullptr, nullptr, raw, xsm);
        }
        grid_sync();
    }
    // state now: h0(511) in SA[0:512], h1(511) in SB[512:], HP[0] = fc_w partials

    // ---- autoregressive decode: s = 1..63 (out col s-1 published in L0 phase) ----
    for (int s = 1; s < FUT; s++) {
        float* Sr = (s & 1) ? g_SA : g_SB;
        float* Sw = (s & 1) ? g_SB : g_SA;
        // pred L0: x = o(s-1) = sum partials + bias; also writes out[:, s-1]
        lstm_step(pw_hh0, 512, Sr, pb_ih0, pb_hh0, nullptr, 0, pw_ih0,
                  g_HP[(s - 1) & 1], (s == 1) ? fc_b : pfc_b, out + (s - 1),
                  g_C, Sw, nullptr, nullptr, raw, xsm);
        grid_sync();
        // pred L1: reads [ph0(s) | ph1(s-1)], writes ph1(s); head partials
        lstm_step(g_WP, 1024, Sw, pb_ih1, pb_hh1, nullptr, 0, nullptr,
                  nullptr, nullptr, nullptr, g_C + 512, Sr + 512,
                  pfc_w, g_HP[s & 1], raw, xsm);
        grid_sync();
    }

    // ---- epilogue: out column 63 from HP[63&1 = 1] ----
    if (blockIdx.x < 8 && tid < 32) {
        const int b = blockIdx.x * 32 + tid;
        float sum = pfc_b[0];
        #pragma unroll
        for (int ut = 0; ut < 16; ut++) sum += g_HP[1][ut][b];
        out[(size_t)b * FUT + 63] = sum;
    }
}

// ---------------------------------------------------------------------------
// Host driver: exactly ONE kernel launch -> 1-node graph (no upload buffer
// growth, no post-teardown residue).
// ---------------------------------------------------------------------------
extern "C" void kernel_launch(void* const* d_in, const int* in_sizes, int n_in,
                              void* d_out, int out_size) {
    (void)in_sizes; (void)n_in; (void)out_size;

    lstm_persist<<<NBLK, 256>>>(
        (const float*)d_in[0],
        (const float*)d_in[2],  (const float*)d_in[3],
        (const float*)d_in[4],  (const float*)d_in[5],
        (const float*)d_in[6],  (const float*)d_in[7],
        (const float*)d_in[8],  (const float*)d_in[9],
        (const float*)d_in[10], (const float*)d_in[11],
        (const float*)d_in[12], (const float*)d_in[13],
        (const float*)d_in[14], (const float*)d_in[15],
        (const float*)d_in[16], (const float*)d_in[17],
        (const float*)d_in[18], (const float*)d_in[19],
        (const float*)d_in[20], (const float*)d_in[21],
        (float*)d_out);
}

// round 7
// speedup vs baseline: 1.0004x; 1.0004x over previous
#include <cuda_runtime.h>
#include <math.h>

// Problem constants (fixed by setup_inputs)
#define BB   256          // batch
#define TT   512          // observed sequence length
#define FUT  64           // future steps
#define KT   64           // K-chunk for GEMM staging
#define NBLK 128          // persistent grid size (<=148 SMs -> all co-resident)

// ---------------------------------------------------------------------------
// Persistent device scratch (module-load allocated; no runtime allocations)
// ---------------------------------------------------------------------------
__device__ float g_SA[BB * 1024];        // ping state  [h0 (512) | h1 (512)]
__device__ float g_SB[BB * 1024];        // pong state
__device__ float g_C [BB * 1024];        // cell states [c0 | c1]
__device__ float g_W1[2048 * 1024];      // [w_ih1 | w_hh1] concat, row-major
__device__ float g_WP[2048 * 1024];      // [pw_ih1 | pw_hh1] concat
__device__ float g_HP[2][16][BB];        // head partial sums (per u-tile), ping-pong
__device__ unsigned g_cnt = 0;           // grid barrier arrival counter
__device__ unsigned g_gen = 0;           // grid barrier generation

// ---------------------------------------------------------------------------
// Software grid barrier (sense-reversing; all CTAs co-resident by construction)
// ---------------------------------------------------------------------------
__device__ __forceinline__ void grid_sync() {
    __syncthreads();
    if (threadIdx.x == 0) {
        __threadfence();
        const unsigned gen = atomicAdd(&g_gen, 0u);
        if (atomicAdd(&g_cnt, 1u) == gridDim.x - 1u) {
            atomicExch(&g_cnt, 0u);
            __threadfence();
            atomicAdd(&g_gen, 1u);
        } else {
            while (atomicAdd(&g_gen, 0u) == gen) { }
        }
        __threadfence();
    }
    __syncthreads();
}

// ---------------------------------------------------------------------------
// Fused LSTM step (device function, single SASS copy via noinline):
//   gates = bias + [x-term] + hin @ W^T ; pointwise c/h update; optional head.
//   W      : [2048][K] row-major (torch gate order i,f,g,o; 512 rows per gate)
//   hin    : state rows of width 1024; uses hin[b*1024 + k], k in [0,K)
//   x modes: xw==null -> none; xpart!=null -> xv = sum16 partials + bias
//            (also writes out column); else xv = xs[b*xstride]
//   headw  : if non-null, write per-u-tile partial dots h.headw into hpOut
// CTA (ublk=blockIdx&15, bblk=blockIdx>>4): 32 batch x 128 gate-rows tile.
// ---------------------------------------------------------------------------
#define MMA4(hv, comp)                                                                   \
    a00 += hv.x * w0.comp; a01 += hv.x * w1.comp; a02 += hv.x * w2.comp; a03 += hv.x * w3.comp; \
    a10 += hv.y * w0.comp; a11 += hv.y * w1.comp; a12 += hv.y * w2.comp; a13 += hv.y * w3.comp; \
    a20 += hv.z * w0.comp; a21 += hv.z * w1.comp; a22 += hv.z * w2.comp; a23 += hv.z * w3.comp; \
    a30 += hv.w * w0.comp; a31 += hv.w * w1.comp; a32 += hv.w * w2.comp; a33 += hv.w * w3.comp;

__device__ __noinline__ void lstm_step(
    const float* __restrict__ W, int K,
    const float* __restrict__ hin,
    const float* __restrict__ bih, const float* __restrict__ bhh,
    const float* __restrict__ xs, int xstride,
    const float* __restrict__ xw,
    const float (* __restrict__ xpart)[BB], const float* __restrict__ xbias_p,
    float* __restrict__ outp,
    float* __restrict__ cbuf, float* __restrict__ hout,
    const float* __restrict__ headw, float (* __restrict__ hpOut)[BB],
    char* raw, float* xsm)
{
    float (*ws)[KT + 4] = reinterpret_cast<float (*)[KT + 4]>(raw);
    float (*hs)[36]     = reinterpret_cast<float (*)[36]>(raw + 128 * (KT + 4) * 4);
    float (*gsm)[33]    = reinterpret_cast<float (*)[33]>(raw);

    const int tid  = threadIdx.x;
    const int ublk = blockIdx.x & 15;
    const int bblk = blockIdx.x >> 4;
    const int u0   = ublk * 32;
    const int b0   = bblk * 32;
    const int tx4  = (tid & 7) * 4;
    const int ty4  = (tid >> 3) * 4;

    __syncthreads();   // protect smem reuse against previous call's tail reads

    // decode-mode scalar input: xv[b] = sum of 16 u-tile partials + head bias
    if (xpart != nullptr && tid < 32) {
        float s = xbias_p[0];
        #pragma unroll
        for (int ut = 0; ut < 16; ut++) s += xpart[ut][b0 + tid];
        xsm[tid] = s;
        if (ublk == 0) outp[(size_t)(b0 + tid) * FUT] = s;   // publish out column
    }

    float a00 = 0.f, a01 = 0.f, a02 = 0.f, a03 = 0.f;
    float a10 = 0.f, a11 = 0.f, a12 = 0.f, a13 = 0.f;
    float a20 = 0.f, a21 = 0.f, a22 = 0.f, a23 = 0.f;
    float a30 = 0.f, a31 = 0.f, a32 = 0.f, a33 = 0.f;

    // W staging assignment: thread -> (local row sr, 32-col half of the K chunk)
    const int sr    = tid >> 1;
    const int shalf = tid & 1;
    const int sg    = sr >> 5;
    const int suu   = sr & 31;
    const float* wrow = W + (size_t)(sg * 512 + u0 + suu) * K + shalf * 32;

    for (int k0 = 0; k0 < K; k0 += KT) {
        #pragma unroll
        for (int i = 0; i < 8; i++) {
            float4 v = *(const float4*)(wrow + k0 + i * 4);
            *(float4*)&ws[sr][shalf * 32 + i * 4] = v;
        }
        #pragma unroll
        for (int rep = 0; rep < 2; rep++) {
            int f  = tid + rep * 256;
            int r  = f & 31;
            int kq = f >> 5;
            float4 v = *(const float4*)(hin + (size_t)(b0 + r) * 1024 + k0 + kq * 4);
            hs[kq * 4 + 0][r] = v.x;
            hs[kq * 4 + 1][r] = v.y;
            hs[kq * 4 + 2][r] = v.z;
            hs[kq * 4 + 3][r] = v.w;
        }
        __syncthreads();

        #pragma unroll 8
        for (int kk = 0; kk < KT; kk += 4) {
            const float4 ha = *(const float4*)&hs[kk + 0][tx4];
            const float4 hb = *(const float4*)&hs[kk + 1][tx4];
            const float4 hc = *(const float4*)&hs[kk + 2][tx4];
            const float4 hd = *(const float4*)&hs[kk + 3][tx4];
            const float4 w0 = *(const float4*)&ws[ty4 + 0][kk];
            const float4 w1 = *(const float4*)&ws[ty4 + 1][kk];
            const float4 w2 = *(const float4*)&ws[ty4 + 2][kk];
            const float4 w3 = *(const float4*)&ws[ty4 + 3][kk];
            MMA4(ha, x); MMA4(hb, y); MMA4(hc, z); MMA4(hd, w);
        }
        __syncthreads();
    }

    // gate exchange through SMEM: gsm[local gate row][local batch]
    gsm[ty4 + 0][tx4 + 0] = a00; gsm[ty4 + 1][tx4 + 0] = a01; gsm[ty4 + 2][tx4 + 0] = a02; gsm[ty4 + 3][tx4 + 0] = a03;
    gsm[ty4 + 0][tx4 + 1] = a10; gsm[ty4 + 1][tx4 + 1] = a11; gsm[ty4 + 2][tx4 + 1] = a12; gsm[ty4 + 3][tx4 + 1] = a13;
    gsm[ty4 + 0][tx4 + 2] = a20; gsm[ty4 + 1][tx4 + 2] = a21; gsm[ty4 + 2][tx4 + 2] = a22; gsm[ty4 + 3][tx4 + 2] = a23;
    gsm[ty4 + 0][tx4 + 3] = a30; gsm[ty4 + 1][tx4 + 3] = a31; gsm[ty4 + 2][tx4 + 3] = a32; gsm[ty4 + 3][tx4 + 3] = a33;
    __syncthreads();

    // pointwise LSTM update: thread (uu, bq) handles unit jb for 4 batches
    const int uu = tid & 31;
    const int bq = tid >> 5;
    const int jb = u0 + uu;

    const bool hasx = (xw != nullptr);
    float wxi = 0.f, wxf = 0.f, wxg = 0.f, wxo = 0.f;
    if (hasx) {
        wxi = xw[jb]; wxf = xw[512 + jb]; wxg = xw[1024 + jb]; wxo = xw[1536 + jb];
    }
    const float bi_ = bih[jb]        + bhh[jb];
    const float bf_ = bih[512 + jb]  + bhh[512 + jb];
    const float bg_ = bih[1024 + jb] + bhh[1024 + jb];
    const float bo_ = bih[1536 + jb] + bhh[1536 + jb];

    float hvals[4];
    #pragma unroll
    for (int p = 0; p < 4; p++) {
        const int bb = bq * 4 + p;
        const int b  = b0 + bb;
        float xv = 0.f;
        if (hasx) xv = (xpart != nullptr) ? xsm[bb] : xs[(size_t)b * xstride];

        float vi = gsm[uu][bb]      + bi_ + xv * wxi;
        float vf = gsm[32 + uu][bb] + bf_ + xv * wxf;
        float vg = gsm[64 + uu][bb] + bg_ + xv * wxg;
        float vo = gsm[96 + uu][bb] + bo_ + xv * wxo;

        const float ig = 1.f / (1.f + expf(-vi));
        const float fg = 1.f / (1.f + expf(-vf));
        const float gg = tanhf(vg);
        const float og = 1.f / (1.f + expf(-vo));

        const size_t idx = (size_t)b * 1024 + jb;
        const float cn = fg * cbuf[idx] + ig * gg;
        cbuf[idx] = cn;
        const float hn = og * tanhf(cn);
        hout[idx] = hn;
        hvals[p] = hn;
    }

    // optional head: deterministic per-u-tile partial dot products
    if (headw != nullptr) {
        const float fwv = headw[jb];
        #pragma unroll
        for (int p = 0; p < 4; p++) {
            float v = hvals[p] * fwv;
            #pragma unroll
            for (int off = 16; off > 0; off >>= 1)
                v += __shfl_xor_sync(0xffffffffu, v, off);
            if (uu == 0) hpOut[ublk][b0 + bq * 4 + p] = v;
        }
    }
}

// ---------------------------------------------------------------------------
// One persistent kernel = one graph node. Internal grid barriers sequence the
// recurrence. Warmup is software-pipelined: phase t = { L1(t-1), L0(t) } with
// a single barrier per phase.
// ---------------------------------------------------------------------------
__global__ __launch_bounds__(256, 1) void lstm_persist(
    const float* __restrict__ x,
    const float* __restrict__ w_ih0, const float* __restrict__ w_hh0,
    const float* __restrict__ b_ih0, const float* __restrict__ b_hh0,
    const float* __restrict__ w_ih1, const float* __restrict__ w_hh1,
    const float* __restrict__ b_ih1, const float* __restrict__ b_hh1,
    const float* __restrict__ fc_w,  const float* __restrict__ fc_b,
    const float* __restrict__ pw_ih0, const float* __restrict__ pw_hh0,
    const float* __restrict__ pb_ih0, const float* __restrict__ pb_hh0,
    const float* __restrict__ pw_ih1, const float* __restrict__ pw_hh1,
    const float* __restrict__ pb_ih1, const float* __restrict__ pb_hh1,
    const float* __restrict__ pfc_w,  const float* __restrict__ pfc_b,
    float* __restrict__ out)
{
    __shared__ __align__(16) char raw[44032];
    __shared__ float xsm[32];

    const int tid  = threadIdx.x;
    const int gtid = blockIdx.x * 256 + tid;
    const int nthr = NBLK * 256;

    // ---- init: zero states, build concat weights ----
    for (int i = gtid; i < BB * 1024; i += nthr) {
        g_SA[i] = 0.f; g_SB[i] = 0.f; g_C[i] = 0.f;
    }
    for (int i = gtid; i < 2048 * 1024; i += nthr) {
        const int j = i >> 10, k = i & 1023;
        g_W1[i] = (k < 512) ? w_ih1[j * 512 + k] : w_hh1[j * 512 + (k - 512)];
        g_WP[i] = (k < 512) ? pw_ih1[j * 512 + k] : pw_hh1[j * 512 + (k - 512)];
    }
    grid_sync();

    // ---- phase 0: L0(0) reads zeros in SA, writes h0(0) into SB[0:512] ----
    lstm_step(w_hh0, 512, g_SA, b_ih0, b_hh0, x, TT, w_ih0,
              nullptr, nullptr, nullptr, g_C, g_SB, nullptr, nullptr, raw, xsm);
    grid_sync();

    // ---- warmup phases t = 1..512: { L1(t-1), L0(t) }, one barrier each ----
    for (int t = 1; t <= TT; t++) {
        float* P = (t & 1) ? g_SB : g_SA;   // read buffer:  [h0(t-1) | h1(t-2)]
        float* Q = (t & 1) ? g_SA : g_SB;   // write buffer
        const bool last = (t == TT);
        // L1(t-1): reads P full, writes h1(t-1) -> Q+512 (head partials on last)
        lstm_step(g_W1, 1024, P, b_ih1, b_hh1, nullptr, 0, nullptr,
                  nullptr, nullptr, nullptr, g_C + 512, Q + 512,
                  last ? fc_w : nullptr, g_HP[0], raw, xsm);
        if (!last) {
            // L0(t): reads P[0:512], writes h0(t) -> Q[0:512]
            lstm_step(w_hh0, 512, P, b_ih0, b_hh0, x + t, TT, w_ih0,
                      nullptr, nullptr, nullptr, g_C, Q, nullptr, nullptr, raw, xsm);
        }
        grid_sync();
    }
    // state now: h0(511) in SA[0:512], h1(511) in SB[512:], HP[0] = fc_w partials

    // ---- autoregressive decode: s = 1..63 (out col s-1 published in L0 phase) ----
    for (int s = 1; s < FUT; s++) {
        float* Sr = (s & 1) ? g_SA : g_SB;
        float* Sw = (s & 1) ? g_SB : g_SA;
        // pred L0: x = o(s-1) = sum partials + bias; also writes out[:, s-1]
        lstm_step(pw_hh0, 512, Sr, pb_ih0, pb_hh0, nullptr, 0, pw_ih0,
                  g_HP[(s - 1) & 1], (s == 1) ? fc_b : pfc_b, out + (s - 1),
                  g_C, Sw, nullptr, nullptr, raw, xsm);
        grid_sync();
        // pred L1: reads [ph0(s) | ph1(s-1)], writes ph1(s); head partials
        lstm_step(g_WP, 1024, Sw, pb_ih1, pb_hh1, nullptr, 0, nullptr,
                  nullptr, nullptr, nullptr, g_C + 512, Sr + 512,
                  pfc_w, g_HP[s & 1], raw, xsm);
        grid_sync();
    }

    // ---- epilogue: out column 63 from HP[63&1 = 1] ----
    if (blockIdx.x < 8 && tid < 32) {
        const int b = blockIdx.x * 32 + tid;
        float sum = pfc_b[0];
        #pragma unroll
        for (int ut = 0; ut < 16; ut++) sum += g_HP[1][ut][b];
        out[(size_t)b * FUT + 63] = sum;
    }
}

// ---------------------------------------------------------------------------
// Host driver: exactly ONE kernel launch -> 1-node graph (no upload buffer
// growth, no post-teardown residue).
// ---------------------------------------------------------------------------
extern "C" void kernel_launch(void* const* d_in, const int* in_sizes, int n_in,
                              void* d_out, int out_size) {
    (void)in_sizes; (void)n_in; (void)out_size;

    lstm_persist<<<NBLK, 256>>>(
        (const float*)d_in[0],
        (const float*)d_in[2],  (const float*)d_in[3],
        (const float*)d_in[4],  (const float*)d_in[5],
        (const float*)d_in[6],  (const float*)d_in[7],
        (const float*)d_in[8],  (const float*)d_in[9],
        (const float*)d_in[10], (const float*)d_in[11],
        (const float*)d_in[12], (const float*)d_in[13],
        (const float*)d_in[14], (const float*)d_in[15],
        (const float*)d_in[16], (const float*)d_in[17],
        (const float*)d_in[18], (const float*)d_in[19],
        (const float*)d_in[20], (const float*)d_in[21],
        (float*)d_out);
}

// round 11
// speedup vs baseline: 2.8782x; 2.8769x over previous
#include <cuda_runtime.h>
#include <cuda_bf16.h>
#include <stdint.h>

#define TSEQ 512
#define FUT  64
#define NCTA 128
#define PITCH 72                       // smem row pitch (bf16 elems) for K-chunk 64
#define APLANE (64*PITCH)              // elems per A plane
#define WPLANE (128*PITCH)             // elems per W plane
#define BUFB   ((2*APLANE + 2*WPLANE)*2)   // 55296 bytes per stage buffer
#define SMEMB  (2*BUFB)                // 110592 bytes dynamic smem

// ---------------- persistent device scratch ----------------
__device__ uint16_t g_W0h[2048*512],  g_W0l[2048*512];    // w_hh0 hi/lo (permuted rows)
__device__ uint16_t g_P0h[2048*512],  g_P0l[2048*512];    // pw_hh0
__device__ uint16_t g_W1h[2048*1024], g_W1l[2048*1024];   // [w_ih1|w_hh1]
__device__ uint16_t g_P1h[2048*1024], g_P1l[2048*1024];   // [pw_ih1|pw_hh1]
__device__ uint16_t g_Sh[2][256*1024], g_Sl[2][256*1024]; // state hi/lo planes [b][h0|h1]
__device__ float    g_Cst[1024*256];                      // cell, unit-major [j][b]
__device__ float    g_B0p[2048], g_B1p[2048], g_BP0p[2048], g_BP1p[2048];
__device__ float    g_X0p[2048], g_XPp[2048];
__device__ float    g_HP[2][16*256];                      // head partials [buf][nt*256+b]
__device__ unsigned g_cnt = 0, g_gen = 0;

// ---------------- helpers ----------------
__device__ __forceinline__ uint32_t smem_u32(const void* p) {
    uint32_t a;
    asm("{ .reg .u64 t; cvta.to.shared.u64 t, %1; cvt.u32.u64 %0, t; }" : "=r"(a) : "l"(p));
    return a;
}
#define CP16(dst, src) \
    asm volatile("cp.async.cg.shared.global [%0], [%1], 16;" :: "r"(dst), "l"(src))
#define LDSM4(r, adr) \
    asm volatile("ldmatrix.sync.aligned.m8n8.x4.shared.b16 {%0,%1,%2,%3}, [%4];" \
        : "=r"((r)[0]), "=r"((r)[1]), "=r"((r)[2]), "=r"((r)[3]) : "r"(adr))
#define MMA(c, a, b0v, b1v) \
    asm volatile("mma.sync.aligned.m16n8k16.row.col.f32.bf16.bf16.f32 " \
        "{%0,%1,%2,%3},{%4,%5,%6,%7},{%8,%9},{%0,%1,%2,%3};" \
        : "+f"((c)[0]), "+f"((c)[1]), "+f"((c)[2]), "+f"((c)[3]) \
        : "r"((a)[0]), "r"((a)[1]), "r"((a)[2]), "r"((a)[3]), "r"(b0v), "r"(b1v))

__device__ __forceinline__ float sigm(float x)  { return __fdividef(1.f, 1.f + __expf(-x)); }
__device__ __forceinline__ float tanh_(float x) { return __fdividef(2.f, 1.f + __expf(-2.f * x)) - 1.f; }

__device__ __forceinline__ void grid_sync() {
    __syncthreads();
    if (threadIdx.x == 0) {
        __threadfence();
        const unsigned gen = atomicAdd(&g_gen, 0u);
        if (atomicAdd(&g_cnt, 1u) == gridDim.x - 1u) {
            atomicExch(&g_cnt, 0u);
            __threadfence();
            atomicAdd(&g_gen, 1u);
        } else {
            while (atomicAdd(&g_gen, 0u) == gen) { }
        }
        __threadfence();
    }
    __syncthreads();
}

// ---------------------------------------------------------------------------
// One fused step: D[64 batch x 128 rows] = S[64,K] @ W[128,K]^T (3-term bf16
// hi/lo mma.sync, fp32 accum) + bias + rank-1 x + LSTM pointwise; writes hi/lo
// state planes + optional head partials. CTA tile from blockIdx: rr=blk&63,
// mt=rr&3 (batch), nt=rr>>2 (row tile; rows permuted R=nt*128+u*4+gate).
// ---------------------------------------------------------------------------
__device__ __noinline__ void run_step(
    const uint16_t* __restrict__ Wh, const uint16_t* __restrict__ Wl, int K,
    const uint16_t* __restrict__ Shr, const uint16_t* __restrict__ Slr,
    const float* __restrict__ biasP, const float* __restrict__ xwP,
    const float* __restrict__ xp,                              // xv = xp[b*TSEQ]
    const float* __restrict__ hpIn, const float* __restrict__ xbias,  // xv = sum+bias
    float* __restrict__ outCol,
    float* __restrict__ cbase,
    uint16_t* __restrict__ Shw, uint16_t* __restrict__ Slw, int uoff,
    const float* __restrict__ headw, float* __restrict__ hpOut,
    char* sm)
{
    const int tid = threadIdx.x, l = tid & 31, w = tid >> 5;
    const int wm = w & 1, wn = w >> 1;
    const int mb = wm * 32, nb = wn * 32;
    const int rr = blockIdx.x & 63;
    const int b0 = (rr & 3) * 64, R0 = (rr >> 2) * 128;
    const uint32_t su = smem_u32(sm);

    float acc[2][4][4];
    #pragma unroll
    for (int i = 0; i < 2; i++)
        #pragma unroll
        for (int j = 0; j < 4; j++)
            #pragma unroll
            for (int k = 0; k < 4; k++) acc[i][j][k] = 0.f;

    const int NC = K >> 6;
    auto stage = [&](int c) {
        const uint32_t sb = su + (c & 1) * BUFB;
        const int k0 = c << 6;
        #pragma unroll
        for (int it = 0; it < 4; it++) {                  // A: 64 rows x 2 planes
            const int idx = tid + it * 256;
            const int pl = idx >> 9, r = (idx >> 3) & 63, sg = idx & 7;
            const uint16_t* src = (pl ? Slr : Shr) + (size_t)(b0 + r) * 1024 + k0 + sg * 8;
            CP16(sb + (pl * APLANE + r * PITCH + sg * 8) * 2, src);
        }
        #pragma unroll
        for (int it = 0; it < 8; it++) {                  // W: 128 rows x 2 planes
            const int idx = tid + it * 256;
            const int pl = idx >> 10, r = (idx >> 3) & 127, sg = idx & 7;
            const uint16_t* src = (pl ? Wl : Wh) + (size_t)(R0 + r) * K + k0 + sg * 8;
            CP16(sb + (2 * APLANE + pl * WPLANE + r * PITCH + sg * 8) * 2, src);
        }
        asm volatile("cp.async.commit_group;");
    };

    __syncthreads();                                      // smem reuse guard
    stage(0);
    const int arow = (l & 15), acol = (l >> 4) << 3;
    const int brow = (l & 7) + ((l >> 4) << 3), bcol = ((l >> 3) & 1) << 3;

    for (int c = 0; c < NC; c++) {
        if (c + 1 < NC) { stage(c + 1); asm volatile("cp.async.wait_group 1;"); }
        else            { asm volatile("cp.async.wait_group 0;"); }
        __syncthreads();
        const uint32_t sb = su + (c & 1) * BUFB;
        #pragma unroll
        for (int ks = 0; ks < 4; ks++) {
            uint32_t Ah[2][4], Al[2][4], Bh[2][4], Bl[2][4];
            #pragma unroll
            for (int mi = 0; mi < 2; mi++) {
                const uint32_t ao = sb + ((mb + mi * 16 + arow) * PITCH + ks * 16 + acol) * 2;
                LDSM4(Ah[mi], ao);
                LDSM4(Al[mi], ao + APLANE * 2);
            }
            #pragma unroll
            for (int ng = 0; ng < 2; ng++) {
                const uint32_t bo = sb + (2 * APLANE) * 2 +
                                    ((nb + ng * 16 + brow) * PITCH + ks * 16 + bcol) * 2;
                LDSM4(Bh[ng], bo);
                LDSM4(Bl[ng], bo + WPLANE * 2);
            }
            #pragma unroll
            for (int mi = 0; mi < 2; mi++)
                #pragma unroll
                for (int nf = 0; nf < 4; nf++) {
                    const int ng = nf >> 1, s2 = (nf & 1) * 2;
                    MMA(acc[mi][nf], Ah[mi], Bh[ng][s2], Bh[ng][s2 + 1]);
                    MMA(acc[mi][nf], Ah[mi], Bl[ng][s2], Bl[ng][s2 + 1]);
                    MMA(acc[mi][nf], Al[mi], Bh[ng][s2], Bh[ng][s2 + 1]);
                }
        }
        __syncthreads();
    }

    // ---- epilogue (scratch overlays stage buffer 0; all MMAs drained) ----
    uint16_t* bhi = (uint16_t*)sm;
    uint16_t* blo = bhi + 64 * 40;
    float* hp_s = (float*)(blo + 64 * 40);
    float* xv_s = hp_s + 256;
    const bool hasx = (xp != nullptr) || (hpIn != nullptr);
    if (tid < 64) {
        const int b = b0 + tid;
        if (xp) xv_s[tid] = xp[(size_t)b * TSEQ];
        else if (hpIn) {
            float s = xbias[0];
            #pragma unroll
            for (int k = 0; k < 16; k++) s += hpIn[k * 256 + b];
            xv_s[tid] = s;
            if (R0 == 0 && outCol) outCol[(size_t)b * FUT] = s;
        }
    }
    __syncthreads();

    float hacc[2][2] = {{0.f, 0.f}, {0.f, 0.f}};
    #pragma unroll
    for (int mi = 0; mi < 2; mi++)
        #pragma unroll
        for (int nf = 0; nf < 4; nf++) {
            const float d0 = acc[mi][nf][0], d1 = acc[mi][nf][1];
            const float d2 = acc[mi][nf][2], d3 = acc[mi][nf][3];
            const float g0 = __shfl_xor_sync(0xffffffffu, d0, 1);
            const float g1 = __shfl_xor_sync(0xffffffffu, d1, 1);
            const float g2 = __shfl_xor_sync(0xffffffffu, d2, 1);
            const float g3 = __shfl_xor_sync(0xffffffffu, d3, 1);
            if (!(l & 1)) {     // even lane of pair owns a full unit (i,f here; g,o from partner)
                const int jloc = (nb + nf * 8 + 2 * (l & 3)) >> 2;
                const int jg = (R0 >> 2) + jloc;
                const float4 b4 = *(const float4*)(biasP + R0 + 4 * jloc);
                float4 x4 = make_float4(0.f, 0.f, 0.f, 0.f);
                if (xwP) x4 = *(const float4*)(xwP + R0 + 4 * jloc);
                const int rl = mb + mi * 16 + (l >> 2);
                #pragma unroll
                for (int h8 = 0; h8 < 2; h8++) {
                    const int row = rl + h8 * 8;
                    float vi = (h8 ? d2 : d0) + b4.x;
                    float vf = (h8 ? d3 : d1) + b4.y;
                    float vg = (h8 ? g2 : g0) + b4.z;
                    float vo = (h8 ? g3 : g1) + b4.w;
                    if (hasx) {
                        const float xv = xv_s[row];
                        vi += xv * x4.x; vf += xv * x4.y;
                        vg += xv * x4.z; vo += xv * x4.w;
                    }
                    float* cp = cbase + (size_t)jg * 256 + b0 + row;
                    const float cn = sigm(vf) * (*cp) + sigm(vi) * tanh_(vg);
                    *cp = cn;
                    const float hn = sigm(vo) * tanh_(cn);
                    if (headw) hacc[mi][h8] += hn * headw[jg];
                    const __nv_bfloat16 hb = __float2bfloat16(hn);
                    const __nv_bfloat16 lb = __float2bfloat16(hn - __bfloat162float(hb));
                    bhi[row * 40 + jloc] = *(const uint16_t*)&hb;
                    blo[row * 40 + jloc] = *(const uint16_t*)&lb;
                }
            }
        }
    if (headw) {
        #pragma unroll
        for (int mi = 0; mi < 2; mi++)
            #pragma unroll
            for (int h8 = 0; h8 < 2; h8++) {
                const float v = hacc[mi][h8] + __shfl_xor_sync(0xffffffffu, hacc[mi][h8], 2);
                if ((l & 3) == 0) hp_s[wn * 64 + mb + mi * 16 + (l >> 2) + h8 * 8] = v;
            }
    }
    __syncthreads();
    {   // coalesced state writeback (16B per thread per plane)
        const int row = tid >> 2, sg = tid & 3;
        const size_t db = (size_t)(b0 + row) * 1024 + uoff + (R0 >> 2) + sg * 8;
        *(uint4*)(Shw + db) = *(const uint4*)(bhi + row * 40 + sg * 8);
        *(uint4*)(Slw + db) = *(const uint4*)(blo + row * 40 + sg * 8);
    }
    if (headw && tid < 64) {
        const float s = hp_s[tid] + hp_s[64 + tid] + hp_s[128 + tid] + hp_s[192 + tid];
        hpOut[(R0 >> 7) * 256 + b0 + tid] = s;
    }
}

// ---------------- persistent kernel: one graph node ----------------
__global__ __launch_bounds__(256, 1) void lstm_mma(
    const float* __restrict__ x,
    const float* __restrict__ w_ih0, const float* __restrict__ w_hh0,
    const float* __restrict__ b_ih0, const float* __restrict__ b_hh0,
    const float* __restrict__ w_ih1, const float* __restrict__ w_hh1,
    const float* __restrict__ b_ih1, const float* __restrict__ b_hh1,
    const float* __restrict__ fc_w,  const float* __restrict__ fc_b,
    const float* __restrict__ pw_ih0, const float* __restrict__ pw_hh0,
    const float* __restrict__ pb_ih0, const float* __restrict__ pb_hh0,
    const float* __restrict__ pw_ih1, const float* __restrict__ pw_hh1,
    const float* __restrict__ pb_ih1, const float* __restrict__ pb_hh1,
    const float* __restrict__ pfc_w,  const float* __restrict__ pfc_b,
    float* __restrict__ out)
{
    extern __shared__ __align__(16) char sm[];
    const int tid = threadIdx.x;
    const int gt = blockIdx.x * 256 + tid, gn = NCTA * 256;

    // ---- init: zero states/cells; permuted hi/lo weights; permuted biases ----
    for (int i = gt; i < 256 * 1024; i += gn) {
        g_Sh[0][i] = 0; g_Sh[1][i] = 0; g_Sl[0][i] = 0; g_Sl[1][i] = 0;
        g_Cst[i] = 0.f;
    }
    for (int i = gt; i < 2048 * 512; i += gn) {
        const int R = i >> 9, k = i & 511;
        const int r = (R & 3) * 512 + (R >> 7) * 32 + ((R & 127) >> 2);
        float v = w_hh0[r * 512 + k];
        __nv_bfloat16 hb = __float2bfloat16(v);
        __nv_bfloat16 lb = __float2bfloat16(v - __bfloat162float(hb));
        g_W0h[i] = *(uint16_t*)&hb; g_W0l[i] = *(uint16_t*)&lb;
        v = pw_hh0[r * 512 + k];
        hb = __float2bfloat16(v); lb = __float2bfloat16(v - __bfloat162float(hb));
        g_P0h[i] = *(uint16_t*)&hb; g_P0l[i] = *(uint16_t*)&lb;
    }
    for (int i = gt; i < 2048 * 1024; i += gn) {
        const int R = i >> 10, k = i & 1023;
        const int r = (R & 3) * 512 + (R >> 7) * 32 + ((R & 127) >> 2);
        float v = (k < 512) ? w_ih1[r * 512 + k] : w_hh1[r * 512 + k - 512];
        __nv_bfloat16 hb = __float2bfloat16(v);
        __nv_bfloat16 lb = __float2bfloat16(v - __bfloat162float(hb));
        g_W1h[i] = *(uint16_t*)&hb; g_W1l[i] = *(uint16_t*)&lb;
        v = (k < 512) ? pw_ih1[r * 512 + k] : pw_hh1[r * 512 + k - 512];
        hb = __float2bfloat16(v); lb = __float2bfloat16(v - __bfloat162float(hb));
        g_P1h[i] = *(uint16_t*)&hb; g_P1l[i] = *(uint16_t*)&lb;
    }
    for (int i = gt; i < 2048; i += gn) {
        const int r = (i & 3) * 512 + (i >> 7) * 32 + ((i & 127) >> 2);
        g_B0p[i]  = b_ih0[r] + b_hh0[r];
        g_B1p[i]  = b_ih1[r] + b_hh1[r];
        g_BP0p[i] = pb_ih0[r] + pb_hh0[r];
        g_BP1p[i] = pb_ih1[r] + pb_hh1[r];
        g_X0p[i]  = w_ih0[r];
        g_XPp[i]  = pw_ih0[r];
    }
    grid_sync();

    const bool isL1 = (blockIdx.x < 64);

    // ---- phase 0: L0(0) (reads zero state) ----
    if (!isL1)
        run_step(g_W0h, g_W0l, 512, g_Sh[0], g_Sl[0], g_B0p, g_X0p, x,
                 nullptr, nullptr, nullptr, g_Cst, g_Sh[1], g_Sl[1], 0,
                 nullptr, nullptr, sm);
    grid_sync();

    // ---- warmup t=1..512: { L1(t-1) || L0(t) }, one barrier per phase ----
    for (int t = 1; t <= TSEQ; t++) {
        const int pi = t & 1, qi = 1 - pi;
        if (isL1)
            run_step(g_W1h, g_W1l, 1024, g_Sh[pi], g_Sl[pi], g_B1p, nullptr,
                     nullptr, nullptr, nullptr, nullptr,
                     g_Cst + 512 * 256, g_Sh[qi], g_Sl[qi], 512,
                     (t == TSEQ) ? fc_w : nullptr, g_HP[0], sm);
        else if (t < TSEQ)
            run_step(g_W0h, g_W0l, 512, g_Sh[pi], g_Sl[pi], g_B0p, g_X0p, x + t,
                     nullptr, nullptr, nullptr, g_Cst, g_Sh[qi], g_Sl[qi], 0,
                     nullptr, nullptr, sm);
        grid_sync();
    }

    // ---- decode s=1..63: phase A = pred L0(s) (+out col s-1); phase B = pred L1(s) ----
    for (int s = 1; s < FUT; s++) {
        const int ri = (s - 1) & 1, wi = s & 1;
        if (!isL1)
            run_step(g_P0h, g_P0l, 512, g_Sh[ri], g_Sl[ri], g_BP0p, g_XPp, nullptr,
                     g_HP[ri], (s == 1) ? fc_b : pfc_b, out + (s - 1),
                     g_Cst, g_Sh[wi], g_Sl[wi], 0, nullptr, nullptr, sm);
        grid_sync();
        if (isL1)
            run_step(g_P1h, g_P1l, 1024, g_Sh[wi], g_Sl[wi], g_BP1p, nullptr,
                     nullptr, nullptr, nullptr, nullptr,
                     g_Cst + 512 * 256, g_Sh[(s + 1) & 1], g_Sl[(s + 1) & 1], 512,
                     pfc_w, g_HP[wi], sm);
        grid_sync();
    }

    // ---- final out column 63 from HP[1] ----
    if (blockIdx.x == 0) {
        float s = pfc_b[0];
        #pragma unroll
        for (int k = 0; k < 16; k++) s += g_HP[1][k * 256 + tid];
        out[(size_t)tid * FUT + 63] = s;
    }
}

// ---------------- host driver: one launch -> one graph node ----------------
extern "C" void kernel_launch(void* const* d_in, const int* in_sizes, int n_in,
                              void* d_out, int out_size) {
    (void)in_sizes; (void)n_in; (void)out_size;
    cudaFuncSetAttribute(lstm_mma, cudaFuncAttributeMaxDynamicSharedMemorySize, SMEMB);
    lstm_mma<<<NCTA, 256, SMEMB>>>(
        (const float*)d_in[0],
        (const float*)d_in[2],  (const float*)d_in[3],
        (const float*)d_in[4],  (const float*)d_in[5],
        (const float*)d_in[6],  (const float*)d_in[7],
        (const float*)d_in[8],  (const float*)d_in[9],
        (const float*)d_in[10], (const float*)d_in[11],
        (const float*)d_in[12], (const float*)d_in[13],
        (const float*)d_in[14], (const float*)d_in[15],
        (const float*)d_in[16], (const float*)d_in[17],
        (const float*)d_in[18], (const float*)d_in[19],
        (const float*)d_in[20], (const float*)d_in[21],
        (float*)d_out);
}